// round 11
// baseline (speedup 1.0000x reference)
#include <cuda_runtime.h>
#include <math_constants.h>
#include <cuda_fp16.h>
#include <cstdint>

#define BATCH 4
#define SEQL 2048
#define DMODEL 512
#define NHEAD 8
#define HDIM 64
#define BHEADS (BATCH * NHEAD)      // 32
#define NROWS (BATCH * SEQL)        // 8192
#define SCALE 0.125f                // 1/sqrt(64)
#define LN_EPS 1e-5f
#define MASKVAL (-65504.0f)         // fp16 lowest finite; exp semantics match -1e9

// -------------------- device scratch (no allocations allowed) ----------------
__device__ uint32_t g_qh16[BHEADS * SEQL * 32];  // packed half2 pairs along dk
__device__ uint32_t g_kh16[BHEADS * SEQL * 32];
__device__ float    g_vh[BHEADS * SEQL * HDIM];  // fp32 V (head layout)
__device__ uint32_t g_vp[BHEADS * 1024 * 64];    // half2 pairs along token: [bh][kp][dv]
__device__ __align__(16) __half g_s16[(size_t)BHEADS * SEQL * SEQL];  // raw S fp16
__device__ float    g_ao[BHEADS * SEQL * HDIM];  // attention output, (B,H,L,DV) flat
__device__ float    g_y[NROWS * DMODEL];         // fc output + residual (pre-LN)

// -------------------- helpers ------------------------------------------------
__device__ __forceinline__ uint32_t f2tf(float x) {
    uint32_t r;
    asm("cvt.rna.tf32.f32 %0, %1;" : "=r"(r) : "f"(x));
    return r;
}

__device__ __forceinline__ uint32_t pack_h2(float lo, float hi) {
    uint32_t r;
    asm("cvt.rn.f16x2.f32 %0, %1, %2;" : "=r"(r) : "f"(hi), "f"(lo));
    return r;
}

__device__ __forceinline__ void mma8(float* c, const uint32_t* a, const uint32_t* b) {
    asm volatile(
        "mma.sync.aligned.m16n8k8.row.col.f32.tf32.tf32.f32 "
        "{%0,%1,%2,%3}, {%4,%5,%6,%7}, {%8,%9}, {%0,%1,%2,%3};\n"
        : "+f"(c[0]), "+f"(c[1]), "+f"(c[2]), "+f"(c[3])
        : "r"(a[0]), "r"(a[1]), "r"(a[2]), "r"(a[3]), "r"(b[0]), "r"(b[1]));
}

__device__ __forceinline__ void mma16(float* c, const uint32_t* a, const uint32_t* b) {
    asm volatile(
        "mma.sync.aligned.m16n8k16.row.col.f32.f16.f16.f32 "
        "{%0,%1,%2,%3}, {%4,%5,%6,%7}, {%8,%9}, {%0,%1,%2,%3};\n"
        : "+f"(c[0]), "+f"(c[1]), "+f"(c[2]), "+f"(c[3])
        : "r"(a[0]), "r"(a[1]), "r"(a[2]), "r"(a[3]), "r"(b[0]), "r"(b[1]));
}

#define CP16(dst_u32, src_ptr) \
    asm volatile("cp.async.cg.shared.global [%0], [%1], 16;\n" :: "r"(dst_u32), "l"(src_ptr))
#define CP_COMMIT() asm volatile("cp.async.commit_group;\n" ::)
#define CP_WAIT1()  asm volatile("cp.async.wait_group 1;\n" ::)
#define CP_WAIT0()  asm volatile("cp.async.wait_group 0;\n" ::)

// ============================================================================
// scores: raw S=(QK^T)*SCALE masked -> g_s16 (fp16) via smem stage with
// coalesced uint4 writes. fp16 mma m16n8k16; 8 heads per block; 2-stage
// cp.async double buffer. Q/K arrive pre-packed half2 from proj.
// smem: 2 x 20480B pipeline bufs + 128 x 272B fp16 stage = 75776 B dyn.
// ============================================================================
__global__ __launch_bounds__(256) void scores_mma_kernel(const int* __restrict__ mask) {
    extern __shared__ uint32_t dynsm32[];
    __shared__ uint32_t Ms[512];                    // mask bitmask
    const int b  = blockIdx.z;
    const int q0 = blockIdx.y * 128;
    const int n0 = blockIdx.x * 128;
    const int tid = threadIdx.x, lane = tid & 31, warp = tid >> 5;
    const int wm = (warp >> 2) * 64, wn = (warp & 3) * 32;
    const int lr = tid >> 2;            // 0..63 (row; +64 second half)
    const int c4 = (tid & 3) * 4;       // u32 col 0,4,8,12
    const uint32_t sbase = (uint32_t)__cvta_generic_to_shared(dynsm32);

    const uint32_t* Qbase = g_qh16 + (size_t)(b * NHEAD) * SEQL * 32;
    const uint32_t* Kbase = g_kh16 + (size_t)(b * NHEAD) * SEQL * 32;

    auto issue = [&](int s) {
        int h = s >> 1, kk = (s & 1) * 16;
        int bi = s & 1;
        const uint32_t* Qp = Qbase + (size_t)h * SEQL * 32 + (size_t)(q0 + lr) * 32 + kk + c4;
        const uint32_t* Kp = Kbase + (size_t)h * SEQL * 32 + (size_t)(n0 + lr) * 32 + kk + c4;
        uint32_t qd = sbase + bi * 20480u + (lr * 20 + c4) * 4u;
        uint32_t kd = qd + 10240u;
#pragma unroll
        for (int rr = 0; rr < 128; rr += 64) {
            CP16(qd + rr * 80u, Qp + (size_t)rr * 32);
            CP16(kd + rr * 80u, Kp + (size_t)rr * 32);
        }
        CP_COMMIT();
    };

    // pack mask bitmask (head-invariant)
    {
        const int* mrow = mask + (size_t)b * SEQL * SEQL;
        for (int w = warp; w < 512; w += 8) {
            int row = w >> 2, cg = w & 3;
            int m = mrow[(size_t)(q0 + row) * SEQL + n0 + cg * 32 + lane];
            unsigned bits = __ballot_sync(0xffffffffu, m == 1);
            if (lane == 0) Ms[w] = bits;
        }
    }

    issue(0);
    issue(1);

    float acc[4][4][4] = {};

    for (int s = 0; s < 16; s++) {
        if (s == 15) { CP_WAIT0(); } else { CP_WAIT1(); }
        __syncthreads();

        const int bi = s & 1;
        const uint32_t* Qb = dynsm32 + bi * 5120;
        const uint32_t* Kb = Qb + 2560;
#pragma unroll
        for (int g = 0; g < 2; g++) {               // two k16 groups per 32-dk slab
            const int kp0 = g * 8 + (lane & 3);
            uint32_t af[4][4], bf[4][2];
#pragma unroll
            for (int tm = 0; tm < 4; tm++) {
                int r0 = wm + tm * 16 + (lane >> 2);
                af[tm][0] = Qb[r0 * 20 + kp0];       af[tm][1] = Qb[(r0 + 8) * 20 + kp0];
                af[tm][2] = Qb[r0 * 20 + kp0 + 4];   af[tm][3] = Qb[(r0 + 8) * 20 + kp0 + 4];
            }
#pragma unroll
            for (int tn = 0; tn < 4; tn++) {
                int rn = wn + tn * 8 + (lane >> 2);
                bf[tn][0] = Kb[rn * 20 + kp0]; bf[tn][1] = Kb[rn * 20 + kp0 + 4];
            }
#pragma unroll
            for (int tm = 0; tm < 4; tm++)
#pragma unroll
                for (int tn = 0; tn < 4; tn++) mma16(acc[tm][tn], af[tm], bf[tn]);
        }

        __syncthreads();                    // pipeline buffer s&1 free for re-issue
        if (s + 2 < 16) issue(s + 2);

        if (s & 1) {
            int h = s >> 1;
            // ---- stage masked fp16 tile into smem (68-u32 padded rows) ----
            __half2* stage2 = (__half2*)(dynsm32 + 10240);
#pragma unroll
            for (int tm = 0; tm < 4; tm++) {
#pragma unroll
                for (int half = 0; half < 2; half++) {
                    int rl = wm + tm * 16 + (lane >> 2) + half * 8;
#pragma unroll
                    for (int tn = 0; tn < 4; tn++) {
                        int cl = wn + tn * 8 + (lane & 3) * 2;
                        unsigned bits = Ms[rl * 4 + (cl >> 5)];
                        int bit = cl & 31;
                        float s0 = acc[tm][tn][half * 2 + 0] * SCALE;
                        float s1 = acc[tm][tn][half * 2 + 1] * SCALE;
                        if ((bits >> bit) & 1u) s0 = MASKVAL;
                        if ((bits >> (bit + 1)) & 1u) s1 = MASKVAL;
                        stage2[rl * 68 + (cl >> 1)] = __floats2half2_rn(s0, s1);
                    }
                }
            }
            __syncthreads();
            // ---- coalesced uint4 writeback: 128 rows x 16 uint4 ----
            {
                const uint4* sp = (const uint4*)(dynsm32 + 10240);
                int row = tid >> 1, seg = (tid & 1) * 8;
                uint4* gp = (uint4*)(g_s16 +
                    ((size_t)(b * NHEAD + h) * SEQL + q0 + row) * SEQL + n0);
#pragma unroll
                for (int i = 0; i < 8; i++) gp[seg + i] = sp[row * 17 + seg + i];
            }
            __syncthreads();                // stage free before next head
#pragma unroll
            for (int tm = 0; tm < 4; tm++)
#pragma unroll
                for (int tn = 0; tn < 4; tn++)
#pragma unroll
                    for (int i = 0; i < 4; i++) acc[tm][tn][i] = 0.f;
        }
    }
}

// ============================================================================
// softmax finalize: read fp16 raw S row, softmax in fp32, write fp32 attn.
// One block per row; 256 threads x 8 elems (one uint4 of halves each).
// ============================================================================
__global__ void softmax_fin_kernel(float* __restrict__ attn) {
    const size_t row = blockIdx.x;
    const __half* hp = g_s16 + row * SEQL;
    float* out = attn + row * SEQL;
    const int tid = threadIdx.x;
    __shared__ float red[8];

    uint4 raw = ((const uint4*)hp)[tid];
    __half2 h2[4] = {*(__half2*)&raw.x, *(__half2*)&raw.y,
                     *(__half2*)&raw.z, *(__half2*)&raw.w};
    float v[8];
#pragma unroll
    for (int i = 0; i < 4; i++) {
        float2 f = __half22float2(h2[i]);
        v[i * 2] = f.x; v[i * 2 + 1] = f.y;
    }
    float m = -CUDART_INF_F;
#pragma unroll
    for (int i = 0; i < 8; i++) m = fmaxf(m, v[i]);
#pragma unroll
    for (int o = 16; o > 0; o >>= 1) m = fmaxf(m, __shfl_xor_sync(0xffffffffu, m, o));
    if ((tid & 31) == 0) red[tid >> 5] = m;
    __syncthreads();
    m = red[0];
#pragma unroll
    for (int i = 1; i < 8; i++) m = fmaxf(m, red[i]);
    __syncthreads();
    float s = 0.f;
#pragma unroll
    for (int i = 0; i < 8; i++) { v[i] = __expf(v[i] - m); s += v[i]; }
#pragma unroll
    for (int o = 16; o > 0; o >>= 1) s += __shfl_xor_sync(0xffffffffu, s, o);
    if ((tid & 31) == 0) red[tid >> 5] = s;
    __syncthreads();
    s = 0.f;
#pragma unroll
    for (int i = 0; i < 8; i++) s += red[i];
    float inv = 1.f / s;
    float4* o4 = (float4*)out;
    o4[tid * 2]     = make_float4(v[0] * inv, v[1] * inv, v[2] * inv, v[3] * inv);
    o4[tid * 2 + 1] = make_float4(v[4] * inv, v[5] * inv, v[6] * inv, v[7] * inv);
}

// ============================================================================
// repack V: fp32 head-layout -> half2 pairs along token. [bh][kp][dv]
// ============================================================================
__global__ void vrepack_kernel() {
    int t = blockIdx.x * 256 + threadIdx.x;        // < 32*1024*64
    int n  = t & 63;
    int kp = (t >> 6) & 1023;
    int bh = t >> 16;
    size_t base = ((size_t)bh * SEQL + 2 * kp) * HDIM + n;
    g_vp[t] = pack_h2(g_vh[base], g_vh[base + HDIM]);
}

// ============================================================================
// PV: out = attn @ V, fp16 mma m16n8k16. attn fp32 (converted in fragment
// gather); V pre-packed half2 token pairs. 2-stage cp.async. (R9 verbatim)
// ============================================================================
__global__ __launch_bounds__(256, 2) void pv_mma_kernel(const float* __restrict__ attn) {
    extern __shared__ float dynsm[];    // 2 bufs x (A 128x36 f32 | Vp 16x72 u32)
    const int bh = blockIdx.y;
    const int q0 = blockIdx.x * 128;
    const float* Ap = attn + (size_t)bh * SEQL * SEQL;
    const uint32_t* Vpg = g_vp + (size_t)bh * 1024 * 64;
    const int tid = threadIdx.x, lane = tid & 31, warp = tid >> 5;
    const int wm = warp * 16;
    const int pr = tid >> 3, pc = (tid & 7) * 4;    // A tile loader
    const int vkp = tid >> 4, vnc = (tid & 15) * 4; // V tile loader (u32)
    const uint32_t sbase = (uint32_t)__cvta_generic_to_shared(dynsm);

    auto issue = [&](int s) {
        int bi = s & 1;
        uint32_t ad = sbase + bi * 23040u + (pr * 36 + pc) * 4u;
        uint32_t vd = sbase + bi * 23040u + 18432u + (vkp * 72 + vnc) * 4u;
        const float* ag = Ap + (size_t)(q0 + pr) * SEQL + s * 32 + pc;
#pragma unroll
        for (int rr = 0; rr < 128; rr += 32) CP16(ad + rr * 144u, ag + (size_t)rr * SEQL);
        const uint32_t* vg = Vpg + (size_t)(s * 16 + vkp) * 64 + vnc;
        CP16(vd, vg);
        CP_COMMIT();
    };

    issue(0);
    issue(1);

    float acc[8][4] = {};
    const int r0 = wm + (lane >> 2);

    for (int s = 0; s < 64; s++) {
        if (s == 63) { CP_WAIT0(); } else { CP_WAIT1(); }
        __syncthreads();

        const int bi = s & 1;
        const float* Ab = dynsm + bi * 5760;
        const uint32_t* Vb = (const uint32_t*)(Ab + 4608);
#pragma unroll
        for (int g = 0; g < 2; g++) {
            const int ka = g * 16 + (lane & 3) * 2;
            const int kb = g * 8 + (lane & 3);
            uint32_t af[4], bf[8][2];
            {
                float2 a0 = *(const float2*)&Ab[r0 * 36 + ka];
                float2 a1 = *(const float2*)&Ab[(r0 + 8) * 36 + ka];
                float2 a2 = *(const float2*)&Ab[r0 * 36 + ka + 8];
                float2 a3 = *(const float2*)&Ab[(r0 + 8) * 36 + ka + 8];
                af[0] = pack_h2(a0.x, a0.y);
                af[1] = pack_h2(a1.x, a1.y);
                af[2] = pack_h2(a2.x, a2.y);
                af[3] = pack_h2(a3.x, a3.y);
            }
#pragma unroll
            for (int tn = 0; tn < 8; tn++) {
                int cn = tn * 8 + (lane >> 2);
                bf[tn][0] = Vb[kb * 72 + cn];
                bf[tn][1] = Vb[(kb + 4) * 72 + cn];
            }
#pragma unroll
            for (int tn = 0; tn < 8; tn++) mma16(acc[tn], af, bf[tn]);
        }

        __syncthreads();
        if (s + 2 < 64) issue(s + 2);
    }

#pragma unroll
    for (int half = 0; half < 2; half++) {
        int row = q0 + wm + (lane >> 2) + half * 8;
#pragma unroll
        for (int tn = 0; tn < 8; tn++) {
            int col = tn * 8 + (lane & 3) * 2;
            *(float2*)&g_ao[((size_t)bh * SEQL + row) * HDIM + col] =
                make_float2(acc[tn][half * 2 + 0], acc[tn][half * 2 + 1]);
        }
    }
}

// ============================================================================
// proj: all three projections in one launch (grid.z selects q/k/v).
// q/k write packed half2 (pairs along dk); v writes fp32. (R9 verbatim)
// ============================================================================
__global__ void proj_mma_kernel(const float* __restrict__ q,
                                const float* __restrict__ k,
                                const float* __restrict__ v,
                                const float* __restrict__ wq_w,
                                const float* __restrict__ wq_b,
                                const float* __restrict__ wv_w,
                                const float* __restrict__ wv_b,
                                uint32_t* __restrict__ oq16,
                                uint32_t* __restrict__ ok16,
                                float* __restrict__ ov) {
    const int which = blockIdx.z;
    const float* A    = which == 0 ? q : (which == 1 ? k : v);
    const float* W    = which == 2 ? wv_w : wq_w;      // faithful bug: k uses wq
    const float* bias = which == 2 ? wv_b : wq_b;

    __shared__ uint32_t As[128][36];
    __shared__ uint32_t Ws[128][36];
    const int n0 = blockIdx.y * 128;
    const int j0 = blockIdx.x * 128;
    const int tid = threadIdx.x, lane = tid & 31, warp = tid >> 5;
    const int wm = (warp >> 2) * 64, wn = (warp & 3) * 32;
    float acc[4][4][4] = {};
    const int lr = tid >> 3;
    const int lc = (tid & 7) * 4;

    for (int ks = 0; ks < DMODEL / 32; ks++) {
#pragma unroll
        for (int rr = 0; rr < 128; rr += 32) {
            float4 av = *(const float4*)&A[(size_t)(n0 + lr + rr) * DMODEL + ks * 32 + lc];
            As[lr + rr][lc + 0] = f2tf(av.x); As[lr + rr][lc + 1] = f2tf(av.y);
            As[lr + rr][lc + 2] = f2tf(av.z); As[lr + rr][lc + 3] = f2tf(av.w);
            float4 wv = *(const float4*)&W[(size_t)(j0 + lr + rr) * DMODEL + ks * 32 + lc];
            Ws[lr + rr][lc + 0] = f2tf(wv.x); Ws[lr + rr][lc + 1] = f2tf(wv.y);
            Ws[lr + rr][lc + 2] = f2tf(wv.z); Ws[lr + rr][lc + 3] = f2tf(wv.w);
        }
        __syncthreads();
#pragma unroll
        for (int k8 = 0; k8 < 4; k8++) {
            const int c0 = k8 * 8 + (lane & 3);
            uint32_t af[4][4], bf[4][2];
#pragma unroll
            for (int tm = 0; tm < 4; tm++) {
                int r0 = wm + tm * 16 + (lane >> 2);
                af[tm][0] = As[r0][c0];     af[tm][1] = As[r0 + 8][c0];
                af[tm][2] = As[r0][c0 + 4]; af[tm][3] = As[r0 + 8][c0 + 4];
            }
#pragma unroll
            for (int tn = 0; tn < 4; tn++) {
                int rn = wn + tn * 8 + (lane >> 2);
                bf[tn][0] = Ws[rn][c0]; bf[tn][1] = Ws[rn][c0 + 4];
            }
#pragma unroll
            for (int tm = 0; tm < 4; tm++)
#pragma unroll
                for (int tn = 0; tn < 4; tn++) mma8(acc[tm][tn], af[tm], bf[tn]);
        }
        __syncthreads();
    }

#pragma unroll
    for (int tm = 0; tm < 4; tm++) {
#pragma unroll
        for (int half = 0; half < 2; half++) {
            int n = n0 + wm + tm * 16 + (lane >> 2) + half * 8;
            int b = n >> 11, l = n & (SEQL - 1);
#pragma unroll
            for (int tn = 0; tn < 4; tn++) {
                int col = j0 + wn + tn * 8 + (lane & 3) * 2;
                int h = col >> 6, dk = col & 63;
                float2 bv = *(const float2*)&bias[col];
                float v0 = acc[tm][tn][half * 2 + 0] + bv.x;
                float v1 = acc[tm][tn][half * 2 + 1] + bv.y;
                size_t rowbase = (size_t)(b * NHEAD + h) * SEQL + l;
                if (which == 2) {
                    *(float2*)&ov[rowbase * HDIM + dk] = make_float2(v0, v1);
                } else {
                    uint32_t* o16 = which == 0 ? oq16 : ok16;
                    o16[rowbase * 32 + (dk >> 1)] = pack_h2(v0, v1);
                }
            }
        }
    }
}

// ============================================================================
// fc: y = x @ fc_w^T + fc_b + residual, faithful .view() permutation fused.
// ============================================================================
__global__ void fc_mma_kernel(const float* __restrict__ W,
                              const float* __restrict__ bias,
                              const float* __restrict__ resid) {
    __shared__ uint32_t As[128][36];
    __shared__ uint32_t Ws[128][36];
    const int n0 = blockIdx.y * 128;
    const int j0 = blockIdx.x * 128;
    const int tid = threadIdx.x, lane = tid & 31, warp = tid >> 5;
    const int wm = (warp >> 2) * 64, wn = (warp & 3) * 32;
    float acc[4][4][4] = {};
    const int lr = tid >> 3;
    const int lc = (tid & 7) * 4;

    for (int ks = 0; ks < DMODEL / 32; ks++) {
#pragma unroll
        for (int rr = 0; rr < 128; rr += 32) {
            int n = n0 + lr + rr;
            int c = ks * 32 + lc;
            int bb = n >> 11, l = n & 2047;
            int h2 = 2 * bb + ((l >> 10) & 1);
            int l3 = (l & 1023) * 2 + (c >> 8);
            int b2 = (c >> 6) & 3;
            int d  = c & 63;
            size_t f = (size_t)h2 * 524288 + (size_t)b2 * 131072 + (size_t)l3 * 64 + d;
            float4 av = *(const float4*)&g_ao[f];
            As[lr + rr][lc + 0] = f2tf(av.x); As[lr + rr][lc + 1] = f2tf(av.y);
            As[lr + rr][lc + 2] = f2tf(av.z); As[lr + rr][lc + 3] = f2tf(av.w);
            float4 wv = *(const float4*)&W[(size_t)(j0 + lr + rr) * DMODEL + ks * 32 + lc];
            Ws[lr + rr][lc + 0] = f2tf(wv.x); Ws[lr + rr][lc + 1] = f2tf(wv.y);
            Ws[lr + rr][lc + 2] = f2tf(wv.z); Ws[lr + rr][lc + 3] = f2tf(wv.w);
        }
        __syncthreads();
#pragma unroll
        for (int k8 = 0; k8 < 4; k8++) {
            const int c0 = k8 * 8 + (lane & 3);
            uint32_t af[4][4], bf[4][2];
#pragma unroll
            for (int tm = 0; tm < 4; tm++) {
                int r0 = wm + tm * 16 + (lane >> 2);
                af[tm][0] = As[r0][c0];     af[tm][1] = As[r0 + 8][c0];
                af[tm][2] = As[r0][c0 + 4]; af[tm][3] = As[r0 + 8][c0 + 4];
            }
#pragma unroll
            for (int tn = 0; tn < 4; tn++) {
                int rn = wn + tn * 8 + (lane >> 2);
                bf[tn][0] = Ws[rn][c0]; bf[tn][1] = Ws[rn][c0 + 4];
            }
#pragma unroll
            for (int tm = 0; tm < 4; tm++)
#pragma unroll
                for (int tn = 0; tn < 4; tn++) mma8(acc[tm][tn], af[tm], bf[tn]);
        }
        __syncthreads();
    }

#pragma unroll
    for (int tm = 0; tm < 4; tm++) {
#pragma unroll
        for (int half = 0; half < 2; half++) {
            int n = n0 + wm + tm * 16 + (lane >> 2) + half * 8;
#pragma unroll
            for (int tn = 0; tn < 4; tn++) {
                int col = j0 + wn + tn * 8 + (lane & 3) * 2;
                float2 bv = *(const float2*)&bias[col];
                float2 rv = *(const float2*)&resid[(size_t)n * DMODEL + col];
                float v0 = acc[tm][tn][half * 2 + 0] + bv.x + rv.x;
                float v1 = acc[tm][tn][half * 2 + 1] + bv.y + rv.y;
                *(float2*)&g_y[(size_t)n * DMODEL + col] = make_float2(v0, v1);
            }
        }
    }
}

// -------------------- layernorm ---------------------------------------------
__global__ void ln_kernel(const float* __restrict__ gam,
                          const float* __restrict__ bet,
                          float* __restrict__ y) {
    const int n = blockIdx.x;
    const float* px = g_y + (size_t)n * DMODEL;
    const int tid = threadIdx.x;
    __shared__ float red[4];
    float v[4];
    float s = 0.f;
#pragma unroll
    for (int i = 0; i < 4; i++) { v[i] = px[tid + i * 128]; s += v[i]; }
#pragma unroll
    for (int o = 16; o > 0; o >>= 1) s += __shfl_xor_sync(0xffffffffu, s, o);
    if ((tid & 31) == 0) red[tid >> 5] = s;
    __syncthreads();
    float mu = (red[0] + red[1] + red[2] + red[3]) * (1.0f / DMODEL);
    __syncthreads();
    float vs = 0.f;
#pragma unroll
    for (int i = 0; i < 4; i++) { float d = v[i] - mu; vs += d * d; }
#pragma unroll
    for (int o = 16; o > 0; o >>= 1) vs += __shfl_xor_sync(0xffffffffu, vs, o);
    if ((tid & 31) == 0) red[tid >> 5] = vs;
    __syncthreads();
    float var = (red[0] + red[1] + red[2] + red[3]) * (1.0f / DMODEL);
    float inv = rsqrtf(var + LN_EPS);
#pragma unroll
    for (int i = 0; i < 4; i++) {
        int c = tid + i * 128;
        y[(size_t)n * DMODEL + c] = (v[i] - mu) * inv * gam[c] + bet[c];
    }
}

// ============================================================================
extern "C" void kernel_launch(void* const* d_in, const int* in_sizes, int n_in,
                              void* d_out, int out_size) {
    const float* q    = (const float*)d_in[0];
    const float* k    = (const float*)d_in[1];
    const float* v    = (const float*)d_in[2];
    const int*   mask = (const int*)d_in[3];
    const float* wq_w = (const float*)d_in[4];
    const float* wq_b = (const float*)d_in[5];
    const float* wv_w = (const float*)d_in[6];
    const float* wv_b = (const float*)d_in[7];
    const float* fc_w = (const float*)d_in[8];
    const float* fc_b = (const float*)d_in[9];
    const float* ln_g = (const float*)d_in[10];
    const float* ln_b = (const float*)d_in[11];

    float* y_out    = (float*)d_out;
    float* attn_out = (float*)d_out + (size_t)NROWS * DMODEL;

    uint32_t *p_qh16, *p_kh16;
    float *p_vh;
    cudaGetSymbolAddress((void**)&p_qh16, g_qh16);
    cudaGetSymbolAddress((void**)&p_kh16, g_kh16);
    cudaGetSymbolAddress((void**)&p_vh, g_vh);

    static bool attrs_set = false;
    if (!attrs_set) {
        cudaFuncSetAttribute(scores_mma_kernel,
                             cudaFuncAttributeMaxDynamicSharedMemorySize, 75776);
        cudaFuncSetAttribute(pv_mma_kernel,
                             cudaFuncAttributeMaxDynamicSharedMemorySize, 46080);
        attrs_set = true;
    }

    dim3 gProj(DMODEL / 128, NROWS / 128, 3);    // (4, 64, 3)
    proj_mma_kernel<<<gProj, 256>>>(q, k, v, wq_w, wq_b, wv_w, wv_b,
                                    p_qh16, p_kh16, p_vh);

    vrepack_kernel<<<(BHEADS * 1024 * 64) / 256, 256>>>();

    dim3 gScores(SEQL / 128, SEQL / 128, BATCH);  // (16, 16, 4)
    scores_mma_kernel<<<gScores, 256, 75776>>>(mask);

    softmax_fin_kernel<<<BHEADS * SEQL, 256>>>(attn_out);

    dim3 gPV(SEQL / 128, BHEADS);   // (16, 32)
    pv_mma_kernel<<<gPV, 256, 46080>>>(attn_out);

    dim3 gFc(DMODEL / 128, NROWS / 128);
    fc_mma_kernel<<<gFc, 256>>>(fc_w, fc_b, q);

    ln_kernel<<<NROWS, 128>>>(ln_g, ln_b, y_out);
}